// round 1
// baseline (speedup 1.0000x reference)
#include <cuda_runtime.h>
#include <math.h>

#define B_SZ    2
#define SEQ_L   2048
#define D_MODEL 1024
#define D_STATE 16
#define D_INNER 2048
#define DT_RANK 64
#define T_TOT   (B_SZ * SEQ_L)          // 4096 tokens

// ---------------- scratch (device globals; no allocations allowed) ----------
__device__ float g_xz[(size_t)T_TOT * 2 * D_INNER];   // in_proj output [tok][4096] (x_in | z)
__device__ float g_xconv[(size_t)T_TOT * D_INNER];    // conv+silu output
__device__ float g_p96[(size_t)T_TOT * 96];           // [dtr(64) | B(16) | C(16)] per token
__device__ float g_dt[(size_t)T_TOT * D_INNER];       // softplus(dt)
__device__ float g_y[(size_t)T_TOT * D_INNER];        // scan output, gated
__device__ float g_wcat[96 * D_INNER];                // concat(x_proj_w, B_proj_w, C_proj_w)

// ---------------- generic fp32 tiled GEMM:  C[M,N] = A[M,K(lda)] * B[N,K]^T --
// EPI: 0 = none, 1 = softplus(acc + bias[n])
template<int EPI>
__global__ void __launch_bounds__(256) sgemm_nt(
    const float* __restrict__ A, int lda,
    const float* __restrict__ Bm,           // [N,K] packed, K contiguous
    float* __restrict__ C, int ldc,
    int M, int N, int K,
    const float* __restrict__ bias)
{
    constexpr int BM = 128, BN = 128, BK = 16;
    __shared__ float As[BK][BM + 4];
    __shared__ float Bs[BK][BN + 4];

    const int m0 = blockIdx.y * BM;
    const int n0 = blockIdx.x * BN;
    const int tid = threadIdx.x;
    const int tx = tid % 16;          // 16 cols of 8
    const int ty = tid / 16;          // 16 rows of 8

    float acc[8][8];
#pragma unroll
    for (int i = 0; i < 8; i++)
#pragma unroll
        for (int j = 0; j < 8; j++) acc[i][j] = 0.f;

    for (int k0 = 0; k0 < K; k0 += BK) {
        // ---- load A tile (128 rows x 16 k), 2 float4 per thread
#pragma unroll
        for (int i = 0; i < 2; i++) {
            int f   = tid + i * 256;
            int row = f >> 2;
            int kc  = (f & 3) * 4;
            float4 v = make_float4(0.f, 0.f, 0.f, 0.f);
            int gr = m0 + row;
            if (gr < M)
                v = *reinterpret_cast<const float4*>(&A[(size_t)gr * lda + k0 + kc]);
            As[kc + 0][row] = v.x; As[kc + 1][row] = v.y;
            As[kc + 2][row] = v.z; As[kc + 3][row] = v.w;
        }
        // ---- load B tile (128 rows x 16 k)
#pragma unroll
        for (int i = 0; i < 2; i++) {
            int f   = tid + i * 256;
            int row = f >> 2;
            int kc  = (f & 3) * 4;
            float4 v = make_float4(0.f, 0.f, 0.f, 0.f);
            int gr = n0 + row;
            if (gr < N)
                v = *reinterpret_cast<const float4*>(&Bm[(size_t)gr * K + k0 + kc]);
            Bs[kc + 0][row] = v.x; Bs[kc + 1][row] = v.y;
            Bs[kc + 2][row] = v.z; Bs[kc + 3][row] = v.w;
        }
        __syncthreads();

#pragma unroll
        for (int kk = 0; kk < BK; kk++) {
            float a[8], bb[8];
            *(float4*)&a[0]  = *(const float4*)&As[kk][ty * 8];
            *(float4*)&a[4]  = *(const float4*)&As[kk][ty * 8 + 4];
            *(float4*)&bb[0] = *(const float4*)&Bs[kk][tx * 8];
            *(float4*)&bb[4] = *(const float4*)&Bs[kk][tx * 8 + 4];
#pragma unroll
            for (int i = 0; i < 8; i++)
#pragma unroll
                for (int j = 0; j < 8; j++)
                    acc[i][j] = fmaf(a[i], bb[j], acc[i][j]);
        }
        __syncthreads();
    }

#pragma unroll
    for (int i = 0; i < 8; i++) {
        int gm = m0 + ty * 8 + i;
        if (gm >= M) continue;
#pragma unroll
        for (int j = 0; j < 8; j++) {
            int gn = n0 + tx * 8 + j;
            if (gn < N) {
                float v = acc[i][j];
                if (EPI == 1) {
                    v += bias[gn];
                    v = (v > 20.f) ? v : log1pf(expf(v));  // softplus
                }
                C[(size_t)gm * ldc + gn] = v;
            }
        }
    }
}

// ---------------- causal depthwise conv (d_conv=4) + SiLU --------------------
__global__ void conv_silu_kernel(const float* __restrict__ conv_w,
                                 const float* __restrict__ conv_b)
{
    int idx = blockIdx.x * blockDim.x + threadIdx.x;
    if (idx >= T_TOT * D_INNER) return;
    int ch  = idx % D_INNER;
    int tok = idx / D_INNER;
    int b = tok / SEQ_L, l = tok % SEQ_L;
    float acc = conv_b[ch];
#pragma unroll
    for (int j = 0; j < 4; j++) {
        int ll = l - 3 + j;
        if (ll >= 0)
            acc = fmaf(conv_w[ch * 4 + j],
                       g_xz[(size_t)(b * SEQ_L + ll) * (2 * D_INNER) + ch], acc);
    }
    g_xconv[idx] = acc / (1.f + expf(-acc));   // silu
}

// ---------------- concat small projection weights into one [96,2048] --------
__global__ void wcat_kernel(const float* __restrict__ xp,
                            const float* __restrict__ bp,
                            const float* __restrict__ cp)
{
    int idx = blockIdx.x * blockDim.x + threadIdx.x;
    if (idx >= 96 * D_INNER) return;
    int r = idx / D_INNER, k = idx % D_INNER;
    float v;
    if (r < 64)      v = xp[r * D_INNER + k];
    else if (r < 80) v = bp[(r - 64) * D_INNER + k];
    else             v = cp[(r - 80) * D_INNER + k];
    g_wcat[idx] = v;
}

// ---------------- selective scan + D-residual + gate -------------------------
// 128 blocks: blockIdx = b * 64 + chunk-of-32-channels.
// 128 threads: 32 channels x 4 state-groups (4 states each).
#define TC 64
__global__ void __launch_bounds__(128) scan_kernel(
    const float* __restrict__ A_log,
    const float* __restrict__ Dp)
{
    __shared__ float Xs [TC][32];
    __shared__ float DTs[TC][32];
    __shared__ float Zs [TC][32];
    __shared__ float BCs[TC][32];   // [B(16) | C(16)]
    __shared__ float Ys [TC][32];

    const int b      = blockIdx.x >> 6;
    const int chBase = (blockIdx.x & 63) * 32;
    const int tid = threadIdx.x;
    const int chl = tid >> 2;       // 0..31
    const int sg  = tid & 3;        // 0..3  (states sg*4 .. sg*4+3)
    const int ch  = chBase + chl;

    const float a0 = -expf(A_log[ch * D_STATE + sg * 4 + 0]);
    const float a1 = -expf(A_log[ch * D_STATE + sg * 4 + 1]);
    const float a2 = -expf(A_log[ch * D_STATE + sg * 4 + 2]);
    const float a3 = -expf(A_log[ch * D_STATE + sg * 4 + 3]);
    float h0 = 0.f, h1 = 0.f, h2 = 0.f, h3 = 0.f;

    for (int t0 = 0; t0 < SEQ_L; t0 += TC) {
        // ---- stage tiles (coalesced)
        for (int i = tid; i < TC * 32; i += 128) {
            int tt = i >> 5, c = i & 31;
            size_t tok = (size_t)(b * SEQ_L + t0 + tt);
            Xs [tt][c] = g_xconv[tok * D_INNER + chBase + c];
            DTs[tt][c] = g_dt   [tok * D_INNER + chBase + c];
            Zs [tt][c] = g_xz   [tok * (2 * D_INNER) + D_INNER + chBase + c];
            BCs[tt][c] = g_p96  [tok * 96 + 64 + c];
        }
        __syncthreads();

        // ---- sequential recurrence over the chunk
        for (int t = 0; t < TC; t++) {
            float x  = Xs [t][chl];
            float dt = DTs[t][chl];
            float dx = dt * x;
            float4 Bv = *(const float4*)&BCs[t][sg * 4];
            float4 Cv = *(const float4*)&BCs[t][16 + sg * 4];
            h0 = fmaf(fmaf(dt, a0, 1.f), h0, dx * Bv.x);
            h1 = fmaf(fmaf(dt, a1, 1.f), h1, dx * Bv.y);
            h2 = fmaf(fmaf(dt, a2, 1.f), h2, dx * Bv.z);
            h3 = fmaf(fmaf(dt, a3, 1.f), h3, dx * Bv.w);
            float yp =  h0 * Cv.x;
            yp = fmaf(h1, Cv.y, yp);
            yp = fmaf(h2, Cv.z, yp);
            yp = fmaf(h3, Cv.w, yp);
            // reduce the 4 state-groups of this channel (lanes differ in sg bits)
            yp += __shfl_xor_sync(0xffffffffu, yp, 1);
            yp += __shfl_xor_sync(0xffffffffu, yp, 2);
            if (sg == 0) Ys[t][chl] = yp;
        }
        __syncthreads();

        // ---- epilogue: y = (y + D*x) * silu(z), coalesced write
        for (int i = tid; i < TC * 32; i += 128) {
            int tt = i >> 5, c = i & 31;
            size_t tok = (size_t)(b * SEQ_L + t0 + tt);
            float yv = fmaf(Dp[chBase + c], Xs[tt][c], Ys[tt][c]);
            float z  = Zs[tt][c];
            yv *= z / (1.f + expf(-z));
            g_y[tok * D_INNER + chBase + c] = yv;
        }
        __syncthreads();
    }
}

// ---------------- launch ------------------------------------------------------
extern "C" void kernel_launch(void* const* d_in, const int* in_sizes, int n_in,
                              void* d_out, int out_size)
{
    const float* x          = (const float*)d_in[0];
    const float* in_proj_w  = (const float*)d_in[1];
    const float* conv_w     = (const float*)d_in[2];
    const float* conv_b     = (const float*)d_in[3];
    const float* A_log      = (const float*)d_in[4];
    const float* Dp         = (const float*)d_in[5];
    const float* dt_proj_w  = (const float*)d_in[6];
    const float* dt_proj_b  = (const float*)d_in[7];
    const float* x_proj_w   = (const float*)d_in[8];
    const float* B_proj_w   = (const float*)d_in[9];
    const float* C_proj_w   = (const float*)d_in[10];
    const float* out_proj_w = (const float*)d_in[11];
    float* out = (float*)d_out;

    float *xz, *xconv, *p96, *dtb, *yb, *wcat;
    cudaGetSymbolAddress((void**)&xz,    g_xz);
    cudaGetSymbolAddress((void**)&xconv, g_xconv);
    cudaGetSymbolAddress((void**)&p96,   g_p96);
    cudaGetSymbolAddress((void**)&dtb,   g_dt);
    cudaGetSymbolAddress((void**)&yb,    g_y);
    cudaGetSymbolAddress((void**)&wcat,  g_wcat);

    // 1) in_proj: xz[4096,4096] = x[4096,1024] @ in_proj_w^T
    {
        dim3 grid((2 * D_INNER) / 128, T_TOT / 128);
        sgemm_nt<0><<<grid, 256>>>(x, D_MODEL, in_proj_w, xz, 2 * D_INNER,
                                   T_TOT, 2 * D_INNER, D_MODEL, nullptr);
    }
    // 2) causal depthwise conv + silu
    conv_silu_kernel<<<(T_TOT * D_INNER + 255) / 256, 256>>>(conv_w, conv_b);

    // 3) concat small weights, then p96[4096,96] = xconv @ wcat^T
    wcat_kernel<<<(96 * D_INNER + 255) / 256, 256>>>(x_proj_w, B_proj_w, C_proj_w);
    {
        dim3 grid(1, T_TOT / 128);
        sgemm_nt<0><<<grid, 256>>>(xconv, D_INNER, wcat, p96, 96,
                                   T_TOT, 96, D_INNER, nullptr);
    }
    // 4) dt[4096,2048] = softplus(dtr @ dt_proj_w^T + b), dtr = p96[:, :64] (lda=96)
    {
        dim3 grid(D_INNER / 128, T_TOT / 128);
        sgemm_nt<1><<<grid, 256>>>(p96, 96, dt_proj_w, dtb, D_INNER,
                                   T_TOT, D_INNER, DT_RANK, dt_proj_b);
    }
    // 5) selective scan + residual + gate
    scan_kernel<<<B_SZ * (D_INNER / 32), 128>>>(A_log, Dp);

    // 6) out_proj: out[4096,1024] = y @ out_proj_w^T
    {
        dim3 grid(D_MODEL / 128, T_TOT / 128);
        sgemm_nt<0><<<grid, 256>>>(yb, D_INNER, out_proj_w, out, D_MODEL,
                                   T_TOT, D_MODEL, D_INNER, nullptr);
    }
}

// round 3
// speedup vs baseline: 2.8276x; 2.8276x over previous
#include <cuda_runtime.h>
#include <cuda_bf16.h>
#include <math.h>
#include <stdint.h>

#define B_SZ    2
#define SEQ_L   2048
#define D_MODEL 1024
#define D_STATE 16
#define D_INNER 2048
#define DT_RANK 64
#define T_TOT   (B_SZ * SEQ_L)          // 4096 tokens

// ---------------- fp32 scratch ----------------------------------------------
__device__ float g_xz[(size_t)T_TOT * 2 * D_INNER];   // in_proj out (x_in | z)
__device__ float g_xconv[(size_t)T_TOT * D_INNER];
__device__ float g_p96[(size_t)T_TOT * 96];           // [dtr(64)|B(16)|C(16)]
__device__ float g_dt[(size_t)T_TOT * D_INNER];

// ---------------- bf16 hi/lo split scratch ----------------------------------
__device__ __nv_bfloat16 g_xh[(size_t)T_TOT * D_MODEL],  g_xl[(size_t)T_TOT * D_MODEL];
__device__ __nv_bfloat16 g_wih[(size_t)2*D_INNER*D_MODEL], g_wil[(size_t)2*D_INNER*D_MODEL];
__device__ __nv_bfloat16 g_xch[(size_t)T_TOT * D_INNER], g_xcl[(size_t)T_TOT * D_INNER];
__device__ __nv_bfloat16 g_wcath[96 * D_INNER],          g_wcatl[96 * D_INNER];
__device__ __nv_bfloat16 g_p96h[(size_t)T_TOT * 96],     g_p96l[(size_t)T_TOT * 96];
__device__ __nv_bfloat16 g_dtph[D_INNER * DT_RANK],      g_dtpl[D_INNER * DT_RANK];
__device__ __nv_bfloat16 g_yh[(size_t)T_TOT * D_INNER],  g_yl[(size_t)T_TOT * D_INNER];
__device__ __nv_bfloat16 g_oph[(size_t)D_MODEL*D_INNER], g_opl[(size_t)D_MODEL*D_INNER];

// ================= helpers ==================================================
__device__ __forceinline__ uint32_t smem_u32(const void* p) {
    uint32_t a;
    asm("{ .reg .u64 t; cvta.to.shared.u64 t, %1; cvt.u32.u64 %0, t; }" : "=r"(a) : "l"(p));
    return a;
}
__device__ __forceinline__ void cp16(uint32_t dst, const void* src, uint32_t sz) {
    asm volatile("cp.async.cg.shared.global [%0], [%1], 16, %2;" :: "r"(dst), "l"(src), "r"(sz) : "memory");
}
#define CP_COMMIT()  asm volatile("cp.async.commit_group;" ::: "memory")

__device__ __forceinline__ void ldsm4(uint32_t& r0, uint32_t& r1, uint32_t& r2, uint32_t& r3, uint32_t a) {
    asm volatile("ldmatrix.sync.aligned.m8n8.x4.shared.b16 {%0,%1,%2,%3}, [%4];"
                 : "=r"(r0), "=r"(r1), "=r"(r2), "=r"(r3) : "r"(a));
}
__device__ __forceinline__ void mma16816(float* d, const uint32_t* a, const uint32_t* b) {
    asm volatile("mma.sync.aligned.m16n8k16.row.col.f32.bf16.bf16.f32 "
                 "{%0,%1,%2,%3}, {%4,%5,%6,%7}, {%8,%9}, {%0,%1,%2,%3};"
                 : "+f"(d[0]), "+f"(d[1]), "+f"(d[2]), "+f"(d[3])
                 : "r"(a[0]), "r"(a[1]), "r"(a[2]), "r"(a[3]), "r"(b[0]), "r"(b[1]));
}
__device__ __forceinline__ void split1(float v, __nv_bfloat16& h, __nv_bfloat16& l) {
    h = __float2bfloat16(v);
    l = __float2bfloat16(v - __bfloat162float(h));
}

// ================= split-bf16 HMMA GEMM =====================================
//  C[M,N] = (Ah+Al)[M,K] * (Bh+Bl)[N,K]^T
//  EPI 0: fp32 | 1: softplus(acc + bias[n]) | 2: fp32 + hi/lo bf16 (guarded N)
//  smem: 2 stages x (Ah|Al|Bh|Bl), each 128 rows x 40 bf16 (80B stride) = 10240B
static const int GEMM_SMEM = 2 * 4 * 10240;   // 81920

template<int EPI>
__global__ void __launch_bounds__(256) gemm_mma(
    const __nv_bfloat16* __restrict__ Ah, const __nv_bfloat16* __restrict__ Al, int lda,
    const __nv_bfloat16* __restrict__ Bh, const __nv_bfloat16* __restrict__ Bl, int ldb,
    float* __restrict__ C, int ldc, int M, int N, int K,
    const float* __restrict__ bias,
    __nv_bfloat16* __restrict__ Chi, __nv_bfloat16* __restrict__ Clo)
{
    extern __shared__ __align__(128) char ds[];
    const uint32_t sb = smem_u32(ds);
    const int tid = threadIdx.x, wid = tid >> 5, lane = tid & 31;
    const int m0 = blockIdx.y * 128, n0 = blockIdx.x * 128;
    const int wm = (wid & 3) * 32;          // warp rows  [wm, wm+32)
    const int wn = (wid >> 2) * 64;         // warp cols  [wn, wn+64)
    const int nbv = min(128, N - n0);       // valid B rows in this tile
    const int NC = K >> 5;

    float d[2][8][4];
#pragma unroll
    for (int i = 0; i < 2; i++)
#pragma unroll
        for (int j = 0; j < 8; j++)
#pragma unroll
            for (int q = 0; q < 4; q++) d[i][j][q] = 0.f;

    auto load_stage = [&](int s, int c) {
        const int k0 = c << 5;
        const uint32_t base = sb + s * 40960;
        for (int i = tid; i < 2048; i += 256) {
            const int mat = i >> 9;
            const int r   = (i >> 2) & 127;
            const int seg = i & 3;
            const uint32_t dst = base + mat * 10240 + r * 80 + seg * 16;
            const __nv_bfloat16* mp; int ld, gr; uint32_t sz = 16;
            if (mat < 2) { mp = mat ? Al : Ah; ld = lda; gr = m0 + r; }
            else         { mp = (mat == 3) ? Bl : Bh; ld = ldb; gr = n0 + r;
                           if (r >= nbv) { sz = 0; gr = n0; } }
            cp16(dst, mp + (size_t)gr * ld + k0 + seg * 8, sz);
        }
        CP_COMMIT();
    };

    load_stage(0, 0);

    for (int c = 0; c < NC; c++) {
        const int s = c & 1;
        if (c + 1 < NC) {
            load_stage(s ^ 1, c + 1);
            asm volatile("cp.async.wait_group 1;" ::: "memory");
        } else {
            asm volatile("cp.async.wait_group 0;" ::: "memory");
        }
        __syncthreads();

        const uint32_t base = sb + s * 40960;
        const uint32_t aH = base, aL = base + 10240, bH = base + 20480, bL = base + 30720;
#pragma unroll
        for (int ks = 0; ks < 2; ks++) {
            const int k0 = ks * 16;
            uint32_t a_h[2][4], a_l[2][4], b_h[8][2], b_l[8][2];
            const uint32_t aoff = (wm + (lane & 15)) * 80 + (k0 + ((lane >> 4) << 3)) * 2;
#pragma unroll
            for (int mi = 0; mi < 2; mi++) {
                ldsm4(a_h[mi][0], a_h[mi][1], a_h[mi][2], a_h[mi][3], aH + aoff + mi * 16 * 80);
                ldsm4(a_l[mi][0], a_l[mi][1], a_l[mi][2], a_l[mi][3], aL + aoff + mi * 16 * 80);
            }
            const int g = lane >> 3;
            const uint32_t boff = (wn + ((g >> 1) << 3) + (lane & 7)) * 80 + (k0 + ((g & 1) << 3)) * 2;
#pragma unroll
            for (int ng = 0; ng < 4; ng++) {
                ldsm4(b_h[ng*2][0], b_h[ng*2][1], b_h[ng*2+1][0], b_h[ng*2+1][1], bH + boff + ng * 16 * 80);
                ldsm4(b_l[ng*2][0], b_l[ng*2][1], b_l[ng*2+1][0], b_l[ng*2+1][1], bL + boff + ng * 16 * 80);
            }
#pragma unroll
            for (int mi = 0; mi < 2; mi++)
#pragma unroll
                for (int ni = 0; ni < 8; ni++) {
                    mma16816(d[mi][ni], a_h[mi], b_h[ni]);
                    mma16816(d[mi][ni], a_h[mi], b_l[ni]);
                    mma16816(d[mi][ni], a_l[mi], b_h[ni]);
                }
        }
        __syncthreads();
    }

    // ---- epilogue ----------------------------------------------------------
#pragma unroll
    for (int mi = 0; mi < 2; mi++) {
#pragma unroll
        for (int ni = 0; ni < 8; ni++) {
            const int col = n0 + wn + ni * 8 + (lane & 3) * 2;
#pragma unroll
            for (int hf = 0; hf < 2; hf++) {
                const int row = m0 + wm + mi * 16 + (lane >> 2) + hf * 8;
                float vx = d[mi][ni][hf * 2 + 0];
                float vy = d[mi][ni][hf * 2 + 1];
                if (EPI == 1) {
                    vx += bias[col];     vy += bias[col + 1];
                    vx = (vx > 20.f) ? vx : log1pf(expf(vx));
                    vy = (vy > 20.f) ? vy : log1pf(expf(vy));
                }
                if (EPI == 2) {
                    const size_t o = (size_t)row * ldc + col;
                    if (col < N) {
                        C[o] = vx;
                        __nv_bfloat16 h, l; split1(vx, h, l);
                        Chi[o] = h; Clo[o] = l;
                    }
                    if (col + 1 < N) {
                        C[o + 1] = vy;
                        __nv_bfloat16 h, l; split1(vy, h, l);
                        Chi[o + 1] = h; Clo[o + 1] = l;
                    }
                } else {
                    float2 v2 = make_float2(vx, vy);
                    *(float2*)&C[(size_t)row * ldc + col] = v2;
                }
            }
        }
    }
}

// ================= small kernels ============================================
__global__ void split_kernel(const float* __restrict__ s, __nv_bfloat16* __restrict__ h,
                             __nv_bfloat16* __restrict__ l, int n)
{
    int i = blockIdx.x * 256 + threadIdx.x;
    if (i < n) { __nv_bfloat16 hh, ll; split1(s[i], hh, ll); h[i] = hh; l[i] = ll; }
}

__global__ void conv_silu_kernel(const float* __restrict__ conv_w,
                                 const float* __restrict__ conv_b)
{
    int idx = blockIdx.x * blockDim.x + threadIdx.x;
    if (idx >= T_TOT * D_INNER) return;
    int ch  = idx % D_INNER;
    int tok = idx / D_INNER;
    int b = tok / SEQ_L, l = tok % SEQ_L;
    float acc = conv_b[ch];
#pragma unroll
    for (int j = 0; j < 4; j++) {
        int ll = l - 3 + j;
        if (ll >= 0)
            acc = fmaf(conv_w[ch * 4 + j],
                       g_xz[(size_t)(b * SEQ_L + ll) * (2 * D_INNER) + ch], acc);
    }
    float s = acc / (1.f + expf(-acc));
    g_xconv[idx] = s;
    __nv_bfloat16 h, lo; split1(s, h, lo);
    g_xch[idx] = h; g_xcl[idx] = lo;
}

__global__ void wcat_kernel(const float* __restrict__ xp,
                            const float* __restrict__ bp,
                            const float* __restrict__ cp)
{
    int idx = blockIdx.x * blockDim.x + threadIdx.x;
    if (idx >= 96 * D_INNER) return;
    int r = idx / D_INNER, k = idx % D_INNER;
    float v;
    if (r < 64)      v = xp[r * D_INNER + k];
    else if (r < 80) v = bp[(r - 64) * D_INNER + k];
    else             v = cp[(r - 80) * D_INNER + k];
    __nv_bfloat16 h, l; split1(v, h, l);
    g_wcath[idx] = h; g_wcatl[idx] = l;
}

// ---------------- selective scan + D-residual + gate ------------------------
#define TCHUNK 64
__global__ void __launch_bounds__(128) scan_kernel(
    const float* __restrict__ A_log,
    const float* __restrict__ Dp)
{
    __shared__ float Xs [TCHUNK][32];
    __shared__ float DTs[TCHUNK][32];
    __shared__ float Zs [TCHUNK][32];
    __shared__ float BCs[TCHUNK][32];
    __shared__ float Ys [TCHUNK][32];

    const int b      = blockIdx.x >> 6;
    const int chBase = (blockIdx.x & 63) * 32;
    const int tid = threadIdx.x;
    const int chl = tid >> 2;
    const int sg  = tid & 3;
    const int ch  = chBase + chl;

    const float a0 = -expf(A_log[ch * D_STATE + sg * 4 + 0]);
    const float a1 = -expf(A_log[ch * D_STATE + sg * 4 + 1]);
    const float a2 = -expf(A_log[ch * D_STATE + sg * 4 + 2]);
    const float a3 = -expf(A_log[ch * D_STATE + sg * 4 + 3]);
    float h0 = 0.f, h1 = 0.f, h2 = 0.f, h3 = 0.f;

    for (int t0 = 0; t0 < SEQ_L; t0 += TCHUNK) {
        for (int i = tid; i < TCHUNK * 32; i += 128) {
            int tt = i >> 5, c = i & 31;
            size_t tok = (size_t)(b * SEQ_L + t0 + tt);
            Xs [tt][c] = g_xconv[tok * D_INNER + chBase + c];
            DTs[tt][c] = g_dt   [tok * D_INNER + chBase + c];
            Zs [tt][c] = g_xz   [tok * (2 * D_INNER) + D_INNER + chBase + c];
            BCs[tt][c] = g_p96  [tok * 96 + 64 + c];
        }
        __syncthreads();

        for (int t = 0; t < TCHUNK; t++) {
            float x  = Xs [t][chl];
            float dt = DTs[t][chl];
            float dx = dt * x;
            float4 Bv = *(const float4*)&BCs[t][sg * 4];
            float4 Cv = *(const float4*)&BCs[t][16 + sg * 4];
            h0 = fmaf(fmaf(dt, a0, 1.f), h0, dx * Bv.x);
            h1 = fmaf(fmaf(dt, a1, 1.f), h1, dx * Bv.y);
            h2 = fmaf(fmaf(dt, a2, 1.f), h2, dx * Bv.z);
            h3 = fmaf(fmaf(dt, a3, 1.f), h3, dx * Bv.w);
            float yp =  h0 * Cv.x;
            yp = fmaf(h1, Cv.y, yp);
            yp = fmaf(h2, Cv.z, yp);
            yp = fmaf(h3, Cv.w, yp);
            yp += __shfl_xor_sync(0xffffffffu, yp, 1);
            yp += __shfl_xor_sync(0xffffffffu, yp, 2);
            if (sg == 0) Ys[t][chl] = yp;
        }
        __syncthreads();

        for (int i = tid; i < TCHUNK * 32; i += 128) {
            int tt = i >> 5, c = i & 31;
            size_t tok = (size_t)(b * SEQ_L + t0 + tt);
            float yv = fmaf(Dp[chBase + c], Xs[tt][c], Ys[tt][c]);
            float z  = Zs[tt][c];
            yv *= z / (1.f + expf(-z));
            __nv_bfloat16 h, l; split1(yv, h, l);
            g_yh[tok * D_INNER + chBase + c] = h;
            g_yl[tok * D_INNER + chBase + c] = l;
        }
        __syncthreads();
    }
}

// ================= launch ====================================================
extern "C" void kernel_launch(void* const* d_in, const int* in_sizes, int n_in,
                              void* d_out, int out_size)
{
    const float* x          = (const float*)d_in[0];
    const float* in_proj_w  = (const float*)d_in[1];
    const float* conv_w     = (const float*)d_in[2];
    const float* conv_b     = (const float*)d_in[3];
    const float* A_log      = (const float*)d_in[4];
    const float* Dp         = (const float*)d_in[5];
    const float* dt_proj_w  = (const float*)d_in[6];
    const float* dt_proj_b  = (const float*)d_in[7];
    const float* x_proj_w   = (const float*)d_in[8];
    const float* B_proj_w   = (const float*)d_in[9];
    const float* C_proj_w   = (const float*)d_in[10];
    const float* out_proj_w = (const float*)d_in[11];
    float* out = (float*)d_out;

    cudaFuncSetAttribute(gemm_mma<0>, cudaFuncAttributeMaxDynamicSharedMemorySize, GEMM_SMEM);
    cudaFuncSetAttribute(gemm_mma<1>, cudaFuncAttributeMaxDynamicSharedMemorySize, GEMM_SMEM);
    cudaFuncSetAttribute(gemm_mma<2>, cudaFuncAttributeMaxDynamicSharedMemorySize, GEMM_SMEM);

    float *xz, *p96, *dtb;
    __nv_bfloat16 *xh, *xl, *wih, *wil, *xch, *xcl, *wcath, *wcatl;
    __nv_bfloat16 *p96h, *p96l, *dtph, *dtpl, *yh, *yl, *oph, *opl;
    cudaGetSymbolAddress((void**)&xz,    g_xz);
    cudaGetSymbolAddress((void**)&p96,   g_p96);
    cudaGetSymbolAddress((void**)&dtb,   g_dt);
    cudaGetSymbolAddress((void**)&xh,    g_xh);
    cudaGetSymbolAddress((void**)&xl,    g_xl);
    cudaGetSymbolAddress((void**)&wih,   g_wih);
    cudaGetSymbolAddress((void**)&wil,   g_wil);
    cudaGetSymbolAddress((void**)&xch,   g_xch);
    cudaGetSymbolAddress((void**)&xcl,   g_xcl);
    cudaGetSymbolAddress((void**)&wcath, g_wcath);
    cudaGetSymbolAddress((void**)&wcatl, g_wcatl);
    cudaGetSymbolAddress((void**)&p96h,  g_p96h);
    cudaGetSymbolAddress((void**)&p96l,  g_p96l);
    cudaGetSymbolAddress((void**)&dtph,  g_dtph);
    cudaGetSymbolAddress((void**)&dtpl,  g_dtpl);
    cudaGetSymbolAddress((void**)&yh,    g_yh);
    cudaGetSymbolAddress((void**)&yl,    g_yl);
    cudaGetSymbolAddress((void**)&oph,   g_oph);
    cudaGetSymbolAddress((void**)&opl,   g_opl);

    // splits
    split_kernel<<<(T_TOT * D_MODEL + 255) / 256, 256>>>(x, xh, xl, T_TOT * D_MODEL);
    split_kernel<<<(2 * D_INNER * D_MODEL + 255) / 256, 256>>>(in_proj_w, wih, wil, 2 * D_INNER * D_MODEL);
    split_kernel<<<(D_INNER * DT_RANK + 255) / 256, 256>>>(dt_proj_w, dtph, dtpl, D_INNER * DT_RANK);
    split_kernel<<<(D_MODEL * D_INNER + 255) / 256, 256>>>(out_proj_w, oph, opl, D_MODEL * D_INNER);
    wcat_kernel<<<(96 * D_INNER + 255) / 256, 256>>>(x_proj_w, B_proj_w, C_proj_w);

    // 1) in_proj
    {
        dim3 grid((2 * D_INNER) / 128, T_TOT / 128);
        gemm_mma<0><<<grid, 256, GEMM_SMEM>>>(xh, xl, D_MODEL, wih, wil, D_MODEL,
                                              xz, 2 * D_INNER, T_TOT, 2 * D_INNER, D_MODEL,
                                              nullptr, nullptr, nullptr);
    }
    // 2) conv + silu (+ split)
    conv_silu_kernel<<<(T_TOT * D_INNER + 255) / 256, 256>>>(conv_w, conv_b);

    // 3) p96 = xconv @ wcat^T  (fp32 + hi/lo)
    {
        dim3 grid(1, T_TOT / 128);
        gemm_mma<2><<<grid, 256, GEMM_SMEM>>>(xch, xcl, D_INNER, wcath, wcatl, D_INNER,
                                              p96, 96, T_TOT, 96, D_INNER,
                                              nullptr, p96h, p96l);
    }
    // 4) dt = softplus(dtr @ dt_proj_w^T + b)
    {
        dim3 grid(D_INNER / 128, T_TOT / 128);
        gemm_mma<1><<<grid, 256, GEMM_SMEM>>>(p96h, p96l, 96, dtph, dtpl, DT_RANK,
                                              dtb, D_INNER, T_TOT, D_INNER, DT_RANK,
                                              dt_proj_b, nullptr, nullptr);
    }
    // 5) scan
    scan_kernel<<<B_SZ * (D_INNER / 32), 128>>>(A_log, Dp);

    // 6) out_proj
    {
        dim3 grid(D_MODEL / 128, T_TOT / 128);
        gemm_mma<0><<<grid, 256, GEMM_SMEM>>>(yh, yl, D_INNER, oph, opl, D_INNER,
                                              out, D_MODEL, T_TOT, D_MODEL, D_INNER,
                                              nullptr, nullptr, nullptr);
    }
}

// round 4
// speedup vs baseline: 3.9688x; 1.4036x over previous
#include <cuda_runtime.h>
#include <cuda_fp16.h>
#include <math.h>
#include <stdint.h>

#define B_SZ    2
#define SEQ_L   2048
#define D_MODEL 1024
#define D_STATE 16
#define D_INNER 2048
#define DT_RANK 64
#define T_TOT   (B_SZ * SEQ_L)          // 4096 tokens

// ---------------- fp32 scratch ----------------------------------------------
__device__ float g_xz[(size_t)T_TOT * 2 * D_INNER];   // in_proj out (x_in | z)
__device__ float g_xconv[(size_t)T_TOT * D_INNER];
__device__ float g_p96[(size_t)T_TOT * 96];           // [dtr(64)|B(16)|C(16)]
__device__ float g_dt[(size_t)T_TOT * D_INNER];

// ---------------- fp16 hi/lo scratch (lo only for A-side operands) ----------
__device__ __half g_xh[(size_t)T_TOT * D_MODEL],  g_xl[(size_t)T_TOT * D_MODEL];
__device__ __half g_wih[(size_t)2*D_INNER*D_MODEL];
__device__ __half g_xch[(size_t)T_TOT * D_INNER], g_xcl[(size_t)T_TOT * D_INNER];
__device__ __half g_wcath[96 * D_INNER];
__device__ __half g_p96h[(size_t)T_TOT * 96],     g_p96l[(size_t)T_TOT * 96];
__device__ __half g_dtph[D_INNER * DT_RANK];
__device__ __half g_yh[(size_t)T_TOT * D_INNER],  g_yl[(size_t)T_TOT * D_INNER];
__device__ __half g_oph[(size_t)D_MODEL*D_INNER];

// ================= helpers ==================================================
__device__ __forceinline__ uint32_t smem_u32(const void* p) {
    uint32_t a;
    asm("{ .reg .u64 t; cvta.to.shared.u64 t, %1; cvt.u32.u64 %0, t; }" : "=r"(a) : "l"(p));
    return a;
}
__device__ __forceinline__ void cp16(uint32_t dst, const void* src, uint32_t sz) {
    asm volatile("cp.async.cg.shared.global [%0], [%1], 16, %2;" :: "r"(dst), "l"(src), "r"(sz) : "memory");
}
#define CP_COMMIT()  asm volatile("cp.async.commit_group;" ::: "memory")

__device__ __forceinline__ void ldsm4(uint32_t& r0, uint32_t& r1, uint32_t& r2, uint32_t& r3, uint32_t a) {
    asm volatile("ldmatrix.sync.aligned.m8n8.x4.shared.b16 {%0,%1,%2,%3}, [%4];"
                 : "=r"(r0), "=r"(r1), "=r"(r2), "=r"(r3) : "r"(a));
}
__device__ __forceinline__ void mma16816h(float* d, const uint32_t* a, const uint32_t* b) {
    asm volatile("mma.sync.aligned.m16n8k16.row.col.f32.f16.f16.f32 "
                 "{%0,%1,%2,%3}, {%4,%5,%6,%7}, {%8,%9}, {%0,%1,%2,%3};"
                 : "+f"(d[0]), "+f"(d[1]), "+f"(d[2]), "+f"(d[3])
                 : "r"(a[0]), "r"(a[1]), "r"(a[2]), "r"(a[3]), "r"(b[0]), "r"(b[1]));
}
__device__ __forceinline__ void split1h(float v, __half& h, __half& l) {
    h = __float2half_rn(v);
    l = __float2half_rn(v - __half2float(h));
}

// ================= fp16 2-term HMMA GEMM ====================================
//  C[M,N] = (Ah+Al)[M,K] * Bh[N,K]^T        (2 MMAs per k-step)
//  EPI 0: fp32 | 1: softplus(acc + bias[n]) | 2: fp32 + hi/lo fp16 (guarded N)
//  smem: 2 stages x (Ah|Al|Bh), each 128 rows x 72 fp16 (144B stride) = 18432B
#define RS     144
#define MATB   (128 * RS)       // 18432
#define STG    (3 * MATB)       // 55296
static const int GEMM_SMEM = 2 * STG;   // 110592

template<int EPI>
__global__ void __launch_bounds__(256) gemm_mma(
    const __half* __restrict__ Ah, const __half* __restrict__ Al, int lda,
    const __half* __restrict__ Bh, int ldb,
    float* __restrict__ C, int ldc, int M, int N, int K,
    const float* __restrict__ bias,
    __half* __restrict__ Chi, __half* __restrict__ Clo)
{
    extern __shared__ __align__(128) char ds[];
    const uint32_t sb = smem_u32(ds);
    const int tid = threadIdx.x, wid = tid >> 5, lane = tid & 31;
    const int m0 = blockIdx.y * 128, n0 = blockIdx.x * 128;
    const int wm = (wid & 3) * 32;          // warp rows  [wm, wm+32)
    const int wn = (wid >> 2) * 64;         // warp cols  [wn, wn+64)
    const int nbv = min(128, N - n0);       // valid B rows in this tile
    const int NC = K >> 6;

    float d[2][8][4];
#pragma unroll
    for (int i = 0; i < 2; i++)
#pragma unroll
        for (int j = 0; j < 8; j++)
#pragma unroll
            for (int q = 0; q < 4; q++) d[i][j][q] = 0.f;

    // 3 mats x 128 rows x 8 x 16B = 3072 cp.async per stage (12/thread)
    auto load_stage = [&](int s, int c) {
        const int k0 = c << 6;
        const uint32_t base = sb + s * STG;
        for (int i = tid; i < 3072; i += 256) {
            const int mat = i >> 10;
            const int r   = (i >> 3) & 127;
            const int seg = i & 7;
            const uint32_t dst = base + mat * MATB + r * RS + seg * 16;
            const __half* mp; int ld, gr; uint32_t sz = 16;
            if (mat == 0)      { mp = Ah; ld = lda; gr = m0 + r; }
            else if (mat == 1) { mp = Al; ld = lda; gr = m0 + r; }
            else               { mp = Bh; ld = ldb; gr = n0 + r;
                                 if (r >= nbv) { sz = 0; gr = n0; } }
            cp16(dst, mp + (size_t)gr * ld + k0 + seg * 8, sz);
        }
        CP_COMMIT();
    };

    load_stage(0, 0);

    for (int c = 0; c < NC; c++) {
        const int s = c & 1;
        if (c + 1 < NC) {
            load_stage(s ^ 1, c + 1);
            asm volatile("cp.async.wait_group 1;" ::: "memory");
        } else {
            asm volatile("cp.async.wait_group 0;" ::: "memory");
        }
        __syncthreads();

        const uint32_t base = sb + s * STG;
        const uint32_t aH = base, aL = base + MATB, bH = base + 2 * MATB;
#pragma unroll
        for (int ks = 0; ks < 4; ks++) {
            const int k0 = ks * 16;
            uint32_t a_h[2][4], a_l[2][4], b_h[8][2];
            const uint32_t aoff = (wm + (lane & 15)) * RS + (k0 + ((lane >> 4) << 3)) * 2;
#pragma unroll
            for (int mi = 0; mi < 2; mi++) {
                ldsm4(a_h[mi][0], a_h[mi][1], a_h[mi][2], a_h[mi][3], aH + aoff + mi * 16 * RS);
                ldsm4(a_l[mi][0], a_l[mi][1], a_l[mi][2], a_l[mi][3], aL + aoff + mi * 16 * RS);
            }
            const int g = lane >> 3;
            const uint32_t boff = (wn + ((g >> 1) << 3) + (lane & 7)) * RS + (k0 + ((g & 1) << 3)) * 2;
#pragma unroll
            for (int ng = 0; ng < 4; ng++)
                ldsm4(b_h[ng*2][0], b_h[ng*2][1], b_h[ng*2+1][0], b_h[ng*2+1][1], bH + boff + ng * 16 * RS);
#pragma unroll
            for (int mi = 0; mi < 2; mi++)
#pragma unroll
                for (int ni = 0; ni < 8; ni++) {
                    mma16816h(d[mi][ni], a_h[mi], b_h[ni]);
                    mma16816h(d[mi][ni], a_l[mi], b_h[ni]);
                }
        }
        __syncthreads();
    }

    // ---- epilogue ----------------------------------------------------------
#pragma unroll
    for (int mi = 0; mi < 2; mi++) {
#pragma unroll
        for (int ni = 0; ni < 8; ni++) {
            const int col = n0 + wn + ni * 8 + (lane & 3) * 2;
#pragma unroll
            for (int hf = 0; hf < 2; hf++) {
                const int row = m0 + wm + mi * 16 + (lane >> 2) + hf * 8;
                float vx = d[mi][ni][hf * 2 + 0];
                float vy = d[mi][ni][hf * 2 + 1];
                if (EPI == 1) {
                    vx += bias[col];     vy += bias[col + 1];
                    vx = (vx > 20.f) ? vx : log1pf(expf(vx));
                    vy = (vy > 20.f) ? vy : log1pf(expf(vy));
                }
                if (EPI == 2) {
                    const size_t o = (size_t)row * ldc + col;
                    if (col < N) {
                        C[o] = vx;
                        __half h, l; split1h(vx, h, l);
                        Chi[o] = h; Clo[o] = l;
                    }
                    if (col + 1 < N) {
                        C[o + 1] = vy;
                        __half h, l; split1h(vy, h, l);
                        Chi[o + 1] = h; Clo[o + 1] = l;
                    }
                } else {
                    float2 v2 = make_float2(vx, vy);
                    *(float2*)&C[(size_t)row * ldc + col] = v2;
                }
            }
        }
    }
}

// ================= small kernels ============================================
__global__ void split_kernel(const float* __restrict__ s, __half* __restrict__ h,
                             __half* __restrict__ l, int n)
{
    int i = blockIdx.x * 256 + threadIdx.x;
    if (i < n) { __half hh, ll; split1h(s[i], hh, ll); h[i] = hh; l[i] = ll; }
}

__global__ void cvt_kernel(const float* __restrict__ s, __half* __restrict__ h, int n)
{
    int i = blockIdx.x * 256 + threadIdx.x;
    if (i < n) h[i] = __float2half_rn(s[i]);
}

__global__ void conv_silu_kernel(const float* __restrict__ conv_w,
                                 const float* __restrict__ conv_b)
{
    int idx = blockIdx.x * blockDim.x + threadIdx.x;
    if (idx >= T_TOT * D_INNER) return;
    int ch  = idx % D_INNER;
    int tok = idx / D_INNER;
    int b = tok / SEQ_L, l = tok % SEQ_L;
    float acc = conv_b[ch];
#pragma unroll
    for (int j = 0; j < 4; j++) {
        int ll = l - 3 + j;
        if (ll >= 0)
            acc = fmaf(conv_w[ch * 4 + j],
                       g_xz[(size_t)(b * SEQ_L + ll) * (2 * D_INNER) + ch], acc);
    }
    float s = acc / (1.f + expf(-acc));
    g_xconv[idx] = s;
    __half h, lo; split1h(s, h, lo);
    g_xch[idx] = h; g_xcl[idx] = lo;
}

__global__ void wcat_kernel(const float* __restrict__ xp,
                            const float* __restrict__ bp,
                            const float* __restrict__ cp)
{
    int idx = blockIdx.x * blockDim.x + threadIdx.x;
    if (idx >= 96 * D_INNER) return;
    int r = idx / D_INNER, k = idx % D_INNER;
    float v;
    if (r < 64)      v = xp[r * D_INNER + k];
    else if (r < 80) v = bp[(r - 64) * D_INNER + k];
    else             v = cp[(r - 80) * D_INNER + k];
    g_wcath[idx] = __float2half_rn(v);
}

// ---------------- selective scan + D-residual + gate ------------------------
#define TCHUNK 64
__global__ void __launch_bounds__(128) scan_kernel(
    const float* __restrict__ A_log,
    const float* __restrict__ Dp)
{
    __shared__ float Xs [TCHUNK][32];
    __shared__ float DTs[TCHUNK][32];
    __shared__ float Zs [TCHUNK][32];
    __shared__ float BCs[TCHUNK][32];
    __shared__ float Ys [TCHUNK][32];

    const int b      = blockIdx.x >> 6;
    const int chBase = (blockIdx.x & 63) * 32;
    const int tid = threadIdx.x;
    const int chl = tid >> 2;
    const int sg  = tid & 3;
    const int ch  = chBase + chl;

    const float a0 = -expf(A_log[ch * D_STATE + sg * 4 + 0]);
    const float a1 = -expf(A_log[ch * D_STATE + sg * 4 + 1]);
    const float a2 = -expf(A_log[ch * D_STATE + sg * 4 + 2]);
    const float a3 = -expf(A_log[ch * D_STATE + sg * 4 + 3]);
    float h0 = 0.f, h1 = 0.f, h2 = 0.f, h3 = 0.f;

    for (int t0 = 0; t0 < SEQ_L; t0 += TCHUNK) {
        for (int i = tid; i < TCHUNK * 32; i += 128) {
            int tt = i >> 5, c = i & 31;
            size_t tok = (size_t)(b * SEQ_L + t0 + tt);
            Xs [tt][c] = g_xconv[tok * D_INNER + chBase + c];
            DTs[tt][c] = g_dt   [tok * D_INNER + chBase + c];
            Zs [tt][c] = g_xz   [tok * (2 * D_INNER) + D_INNER + chBase + c];
            BCs[tt][c] = g_p96  [tok * 96 + 64 + c];
        }
        __syncthreads();

        for (int t = 0; t < TCHUNK; t++) {
            float x  = Xs [t][chl];
            float dt = DTs[t][chl];
            float dx = dt * x;
            float4 Bv = *(const float4*)&BCs[t][sg * 4];
            float4 Cv = *(const float4*)&BCs[t][16 + sg * 4];
            h0 = fmaf(fmaf(dt, a0, 1.f), h0, dx * Bv.x);
            h1 = fmaf(fmaf(dt, a1, 1.f), h1, dx * Bv.y);
            h2 = fmaf(fmaf(dt, a2, 1.f), h2, dx * Bv.z);
            h3 = fmaf(fmaf(dt, a3, 1.f), h3, dx * Bv.w);
            float yp =  h0 * Cv.x;
            yp = fmaf(h1, Cv.y, yp);
            yp = fmaf(h2, Cv.z, yp);
            yp = fmaf(h3, Cv.w, yp);
            yp += __shfl_xor_sync(0xffffffffu, yp, 1);
            yp += __shfl_xor_sync(0xffffffffu, yp, 2);
            if (sg == 0) Ys[t][chl] = yp;
        }
        __syncthreads();

        for (int i = tid; i < TCHUNK * 32; i += 128) {
            int tt = i >> 5, c = i & 31;
            size_t tok = (size_t)(b * SEQ_L + t0 + tt);
            float yv = fmaf(Dp[chBase + c], Xs[tt][c], Ys[tt][c]);
            float z  = Zs[tt][c];
            yv *= z / (1.f + expf(-z));
            __half h, l; split1h(yv, h, l);
            g_yh[tok * D_INNER + chBase + c] = h;
            g_yl[tok * D_INNER + chBase + c] = l;
        }
        __syncthreads();
    }
}

// ================= launch ====================================================
extern "C" void kernel_launch(void* const* d_in, const int* in_sizes, int n_in,
                              void* d_out, int out_size)
{
    const float* x          = (const float*)d_in[0];
    const float* in_proj_w  = (const float*)d_in[1];
    const float* conv_w     = (const float*)d_in[2];
    const float* conv_b     = (const float*)d_in[3];
    const float* A_log      = (const float*)d_in[4];
    const float* Dp         = (const float*)d_in[5];
    const float* dt_proj_w  = (const float*)d_in[6];
    const float* dt_proj_b  = (const float*)d_in[7];
    const float* x_proj_w   = (const float*)d_in[8];
    const float* B_proj_w   = (const float*)d_in[9];
    const float* C_proj_w   = (const float*)d_in[10];
    const float* out_proj_w = (const float*)d_in[11];
    float* out = (float*)d_out;

    cudaFuncSetAttribute(gemm_mma<0>, cudaFuncAttributeMaxDynamicSharedMemorySize, GEMM_SMEM);
    cudaFuncSetAttribute(gemm_mma<1>, cudaFuncAttributeMaxDynamicSharedMemorySize, GEMM_SMEM);
    cudaFuncSetAttribute(gemm_mma<2>, cudaFuncAttributeMaxDynamicSharedMemorySize, GEMM_SMEM);

    float *xz, *p96, *dtb;
    __half *xh, *xl, *wih, *xch, *xcl, *wcath;
    __half *p96h, *p96l, *dtph, *yh, *yl, *oph;
    cudaGetSymbolAddress((void**)&xz,    g_xz);
    cudaGetSymbolAddress((void**)&p96,   g_p96);
    cudaGetSymbolAddress((void**)&dtb,   g_dt);
    cudaGetSymbolAddress((void**)&xh,    g_xh);
    cudaGetSymbolAddress((void**)&xl,    g_xl);
    cudaGetSymbolAddress((void**)&wih,   g_wih);
    cudaGetSymbolAddress((void**)&xch,   g_xch);
    cudaGetSymbolAddress((void**)&xcl,   g_xcl);
    cudaGetSymbolAddress((void**)&wcath, g_wcath);
    cudaGetSymbolAddress((void**)&p96h,  g_p96h);
    cudaGetSymbolAddress((void**)&p96l,  g_p96l);
    cudaGetSymbolAddress((void**)&dtph,  g_dtph);
    cudaGetSymbolAddress((void**)&yh,    g_yh);
    cudaGetSymbolAddress((void**)&yl,    g_yl);
    cudaGetSymbolAddress((void**)&oph,   g_oph);

    // splits / conversions
    split_kernel<<<(T_TOT * D_MODEL + 255) / 256, 256>>>(x, xh, xl, T_TOT * D_MODEL);
    cvt_kernel<<<(2 * D_INNER * D_MODEL + 255) / 256, 256>>>(in_proj_w, wih, 2 * D_INNER * D_MODEL);
    cvt_kernel<<<(D_INNER * DT_RANK + 255) / 256, 256>>>(dt_proj_w, dtph, D_INNER * DT_RANK);
    cvt_kernel<<<(D_MODEL * D_INNER + 255) / 256, 256>>>(out_proj_w, oph, D_MODEL * D_INNER);
    wcat_kernel<<<(96 * D_INNER + 255) / 256, 256>>>(x_proj_w, B_proj_w, C_proj_w);

    // 1) in_proj
    {
        dim3 grid((2 * D_INNER) / 128, T_TOT / 128);
        gemm_mma<0><<<grid, 256, GEMM_SMEM>>>(xh, xl, D_MODEL, wih, D_MODEL,
                                              xz, 2 * D_INNER, T_TOT, 2 * D_INNER, D_MODEL,
                                              nullptr, nullptr, nullptr);
    }
    // 2) conv + silu (+ split)
    conv_silu_kernel<<<(T_TOT * D_INNER + 255) / 256, 256>>>(conv_w, conv_b);

    // 3) p96 = xconv @ wcat^T  (fp32 + hi/lo)
    {
        dim3 grid(1, T_TOT / 128);
        gemm_mma<2><<<grid, 256, GEMM_SMEM>>>(xch, xcl, D_INNER, wcath, D_INNER,
                                              p96, 96, T_TOT, 96, D_INNER,
                                              nullptr, p96h, p96l);
    }
    // 4) dt = softplus(dtr @ dt_proj_w^T + b)
    {
        dim3 grid(D_INNER / 128, T_TOT / 128);
        gemm_mma<1><<<grid, 256, GEMM_SMEM>>>(p96h, p96l, 96, dtph, DT_RANK,
                                              dtb, D_INNER, T_TOT, D_INNER, DT_RANK,
                                              dt_proj_b, nullptr, nullptr);
    }
    // 5) scan
    scan_kernel<<<B_SZ * (D_INNER / 32), 128>>>(A_log, Dp);

    // 6) out_proj
    {
        dim3 grid(D_MODEL / 128, T_TOT / 128);
        gemm_mma<0><<<grid, 256, GEMM_SMEM>>>(yh, yl, D_INNER, oph, D_INNER,
                                              out, D_MODEL, T_TOT, D_MODEL, D_INNER,
                                              nullptr, nullptr, nullptr);
    }
}